// round 2
// baseline (speedup 1.0000x reference)
#include <cuda_runtime.h>
#include <cstdint>

// BiologicalWorkingMemory: B x (S=8 slots, D=64 dims) fused update.
// Layout: 8 lanes per batch (lane r holds elements [r*8, r*8+8) of every slot),
// 4 batches per warp, 128 threads/block -> 16 batches/block.
//
// Round-2 change: the 56 sequential interference pairs no longer do cross-lane
// reductions. The 8x8 Gram matrix is computed once (36 pipelined reductions),
// then maintained by exact scalar recurrences:
//   v_i -= c v_j  =>  G[i][k] -= c G[j][k] (k!=i),
//                     G[i][i] += c*(c*G[j][j] - 2*G[i][j]).
// Critical path per pair: FMA -> mul -> rsqrt -> mul (~30 cyc) instead of a
// 3-step shfl reduction (~110 cyc).

static __device__ __forceinline__ float gsum8(float v) {
    v += __shfl_xor_sync(0xffffffffu, v, 1);
    v += __shfl_xor_sync(0xffffffffu, v, 2);
    v += __shfl_xor_sync(0xffffffffu, v, 4);
    return v;
}

// symmetric index for a<=b into 36-entry triangle
#define GIDX(a, b) ((a) * 8 - (a) * ((a) + 1) / 2 + (b))
#define GSYM(a, b) ((a) <= (b) ? GIDX(a, b) : GIDX(b, a))

__global__ __launch_bounds__(128, 3) void wm_kernel(
    const float* __restrict__ mem,        // (B,8,64)
    const float* __restrict__ act_in,     // (B,8)
    const float* __restrict__ gate_in,    // (B,8)
    const float* __restrict__ thr_in,     // (B,8)
    const float* __restrict__ refresh_in, // (B,8)
    const float* __restrict__ intf,       // (B,8,8)
    const float* __restrict__ maint_in,   // (B,8)
    const float* __restrict__ x_in,       // (B,64)
    const float* __restrict__ gsig_in,    // (B,8)
    const float* __restrict__ rsig_in,    // (B,8)
    const void* __restrict__ dt_ptr,
    float* __restrict__ out,
    int B)
{
    const unsigned FULL = 0xffffffffu;
    const int lane = threadIdx.x & 31;
    const int warp = blockIdx.x * (blockDim.x >> 5) + (threadIdx.x >> 5);
    const int grp  = lane >> 3;   // batch within warp
    const int r    = lane & 7;    // slot rank / element-chunk rank
    const int b    = warp * 4 + grp;
    const bool valid = (b < B);
    const int bb = valid ? b : (B - 1);

    // dt may arrive as int32 or float32 scalar; decode by bit-pattern heuristic.
    float dtf;
    {
        int di = *(const int*)dt_ptr;
        dtf = (di > -16777216 && di < 16777216) ? (float)di : __int_as_float(di);
    }

    // ---- per-slot scalars: lane r owns slot r of its batch ----
    const size_t sb = (size_t)bb * 8 + r;
    const float act0 = act_in[sb];
    const float gate = gate_in[sb];
    const float thr  = thr_in[sb];
    const float rstr = refresh_in[sb];
    const float maint= maint_in[sb];
    const float gsig = gsig_in[sb];
    const float rsig = rsig_in[sb];

    // interference row r (8 floats)
    const float4* ip = (const float4*)(intf + (size_t)bb * 64 + (size_t)r * 8);
    const float4 I0 = ip[0], I1 = ip[1];
    const float Irow[8] = {I0.x, I0.y, I0.z, I0.w, I1.x, I1.y, I1.z, I1.w};

    // inputs: lane r holds elements [r*8, r*8+8)
    const float4* xp = (const float4*)(x_in + (size_t)bb * 64 + (size_t)r * 8);
    const float4 xA = xp[0], xB = xp[1];

    // ---- load memory slots, apply decay ----
    const float4* mp = (const float4*)(mem + (size_t)bb * 512);
    float4 mA[8], mB[8];
#pragma unroll
    for (int s = 0; s < 8; s++) {
        float4 a4 = mp[s * 16 + r * 2];
        float4 b4 = mp[s * 16 + r * 2 + 1];
        a4.x *= 0.95f; a4.y *= 0.95f; a4.z *= 0.95f; a4.w *= 0.95f;
        b4.x *= 0.95f; b4.y *= 0.95f; b4.z *= 0.95f; b4.w *= 0.95f;
        mA[s] = a4; mB[s] = b4;
    }

    // ---- full Gram matrix: 36 independent reductions (pipelined shuffles) ----
    float G[36];
#pragma unroll
    for (int a = 0; a < 8; a++) {
#pragma unroll
        for (int c = a; c < 8; c++) {
            const float4 aA = mA[a], aB = mB[a];
            const float4 cA = mA[c], cB = mB[c];
            float p = ((aA.x * cA.x + aA.y * cA.y) + (aA.z * cA.z + aA.w * cA.w))
                    + ((aB.x * cB.x + aB.y * cB.y) + (aB.z * cB.z + aB.w * cB.w));
            G[GIDX(a, c)] = gsum8(p);
        }
    }

    // ---- activity decay + masks ----
    const float adec = act0 * 0.9f;
    const unsigned actBall = __ballot_sync(FULL, adec > 0.1f);
    const unsigned actMask = (actBall >> (grp * 8)) & 0xffu;
    const unsigned avBall = __ballot_sync(FULL, act0 < 0.2f);
    const unsigned avMask = (avBall >> (grp * 8)) & 0xffu;

    // ---- target slot: argmin with jnp tie-break (lowest index) ----
    const float INF = __int_as_float(0x7f800000);
    float key = avMask ? ((act0 < 0.2f) ? act0 : INF) : act0;
    int idx = r;
#pragma unroll
    for (int off = 1; off < 8; off <<= 1) {
        float ov = __shfl_xor_sync(FULL, key, off);
        int   oi = __shfl_xor_sync(FULL, idx, off);
        if (ov < key || (ov == key && oi < idx)) { key = ov; idx = oi; }
    }
    const int ts = idx;  // uniform within group

    // ---- sequential interference: 56 ordered pair updates, scalar recurrence ----
#pragma unroll
    for (int i = 0; i < 8; i++) {
        // hoist interference coefficients for this row (shfl latency hidden)
        float Kc[8];
#pragma unroll
        for (int j = 0; j < 8; j++) {
            if (j == i) { Kc[j] = 0.0f; continue; }
            const float Iv = __shfl_sync(FULL, Irow[j], i, 8);
            const bool cond = ((actMask >> i) & 1u) && ((actMask >> j) & 1u);
            Kc[j] = cond ? 0.1f * Iv : 0.0f;
        }
#pragma unroll
        for (int j = 0; j < 8; j++) {
            if (i == j) continue;
            const float Gij = G[GSYM(i, j)];
            const float Gjj = G[GIDX(j, j)];
            // sim = Gij / (ni*nj + 1e-6); 1e-6 << ulp -> rsqrt form
            const float c = Kc[j] * Gij * rsqrtf(G[GIDX(i, i)] * Gjj);
            // G[i][i] uses OLD Gij
            const float GiiNew = fmaf(c, fmaf(c, Gjj, -2.0f * Gij), G[GIDX(i, i)]);
#pragma unroll
            for (int k = 0; k < 8; k++) {
                if (k == i) continue;
                G[GSYM(i, k)] = fmaf(-c, G[GSYM(j, k)], G[GSYM(i, k)]);
            }
            G[GIDX(i, i)] = GiiNew;
            // vector update (off the critical path)
            mA[i].x = fmaf(-c, mA[j].x, mA[i].x);
            mA[i].y = fmaf(-c, mA[j].y, mA[i].y);
            mA[i].z = fmaf(-c, mA[j].z, mA[i].z);
            mA[i].w = fmaf(-c, mA[j].w, mA[i].w);
            mB[i].x = fmaf(-c, mB[j].x, mB[i].x);
            mB[i].y = fmaf(-c, mB[j].y, mB[i].y);
            mB[i].z = fmaf(-c, mB[j].z, mB[i].z);
            mB[i].w = fmaf(-c, mB[j].w, mB[i].w);
        }
    }

    // ---- gating / write ----
    const float gv = 0.7f * gate + 0.3f * __saturatef(gsig);
    const float gs = __shfl_sync(FULL, gv, ts, 8);
    const float th = __shfl_sync(FULL, thr, ts, 8);
    const bool write = gs > th;

    const float in2 = gsum8(((xA.x * xA.x + xA.y * xA.y) + (xA.z * xA.z + xA.w * xA.w))
                          + ((xB.x * xB.x + xB.y * xB.y) + (xB.z * xB.z + xB.w * xB.w)));
    const float inorm = sqrtf(in2);

    float a = adec;
    if (write && r == ts) a = inorm;

    // ---- refresh ----
    const float ru = __saturatef(rsig);
    const float rs = (ru > 0.1f) ? rstr * ru : 0.0f;
    a += rs;

    // ---- maintenance ----
    const float mc = (a > 0.1f)
        ? fmaf(fmaf(0.5f, a, -maint), 0.1f * dtf, maint)
        : maint * 0.95f;

    // ---- capacity limiting: rank active slots ascending (stable ties) ----
    float ab[8];
#pragma unroll
    for (int s = 0; s < 8; s++) ab[s] = __shfl_sync(FULL, a, s, 8);
    const unsigned activeBall = __ballot_sync(FULL, a > 0.1f);
    const unsigned activeMask = (activeBall >> (grp * 8)) & 0xffu;
    const int ndeact = __popc(activeMask) - 4;
    int rank = 0;
#pragma unroll
    for (int s = 0; s < 8; s++) {
        const bool sa = (activeMask >> s) & 1u;
        if (sa && (ab[s] < a || (ab[s] == a && s < r))) rank++;
    }
    const bool active_r = (activeMask >> r) & 1u;
    const bool deact = active_r && (rank < ndeact);
    const float afin = deact ? a * 0.5f : a;
    const unsigned deBall = __ballot_sync(FULL, deact);
    const unsigned deMask = (deBall >> (grp * 8)) & 0xffu;

    // broadcast per-slot refresh scales for the m pass
    float rsb[8];
#pragma unroll
    for (int s = 0; s < 8; s++) rsb[s] = __shfl_sync(FULL, rs, s, 8);

    // ---- fused m epilogue: write-blend, refresh scale, deact scale, store ----
    const float wgt = write ? gs * 0.3f : 0.0f;
    if (valid) {
        float4* op = (float4*)(out + (size_t)b * 512);
#pragma unroll
        for (int s = 0; s < 8; s++) {
            const float scale = (1.0f + rsb[s]) * (((deMask >> s) & 1u) ? 0.7f : 1.0f);
            const float take = (s == ts) ? wgt : 0.0f;
            float4 vA = mA[s], vB = mB[s];
            vA.x = (vA.x + take * (xA.x - vA.x)) * scale;
            vA.y = (vA.y + take * (xA.y - vA.y)) * scale;
            vA.z = (vA.z + take * (xA.z - vA.z)) * scale;
            vA.w = (vA.w + take * (xA.w - vA.w)) * scale;
            vB.x = (vB.x + take * (xB.x - vB.x)) * scale;
            vB.y = (vB.y + take * (xB.y - vB.y)) * scale;
            vB.z = (vB.z + take * (xB.z - vB.z)) * scale;
            vB.w = (vB.w + take * (xB.w - vB.w)) * scale;
            op[s * 16 + r * 2]     = vA;
            op[s * 16 + r * 2 + 1] = vB;
        }
    }

    // ---- per-batch reductions + scalar outputs ----
    const float tot  = gsum8(afin);
    const float msum = gsum8(mc);
    const unsigned loadBall = __ballot_sync(FULL, afin > 0.1f);
    const int mload = __popc((loadBall >> (grp * 8)) & 0xffu);

    const size_t OA  = (size_t)B * 512;      // m size
    const size_t SB8 = (size_t)B * 8;
    if (valid) {
        out[OA + (size_t)b * 8 + r]           = afin;  // a
        out[OA + SB8 + (size_t)b * 8 + r]     = gv;    // g
        out[OA + 2 * SB8 + (size_t)b * 8 + r] = mc;    // mc
        if (r == 0) {
            out[OA + 3 * SB8 + (size_t)b]                 = (float)mload;
            out[OA + 3 * SB8 + (size_t)B + (size_t)b]     = tot;
            out[OA + 3 * SB8 + 2 * (size_t)B + (size_t)b] = msum * 0.125f;
        }
    }
}

extern "C" void kernel_launch(void* const* d_in, const int* in_sizes, int n_in,
                              void* d_out, int out_size)
{
    const int B = in_sizes[0] / 512;   // B*S*D / (8*64)
    const int threads = 128;           // 4 warps * 4 batches = 16 batches/block
    const int batchesPerBlock = 16;
    const int grid = (B + batchesPerBlock - 1) / batchesPerBlock;
    wm_kernel<<<grid, threads>>>(
        (const float*)d_in[0], (const float*)d_in[1], (const float*)d_in[2],
        (const float*)d_in[3], (const float*)d_in[4], (const float*)d_in[5],
        (const float*)d_in[6], (const float*)d_in[7], (const float*)d_in[8],
        (const float*)d_in[9], (const void*)d_in[10],
        (float*)d_out, B);
}